// round 1
// baseline (speedup 1.0000x reference)
#include <cuda_runtime.h>
#include <math.h>

#define NN   50000
#define EE   800000
#define FIN  64
#define HID  128
#define HEADS 4
#define HOUT 512           // HEADS*HID
#define LAYERS 3
#define NEG_SLOPE 0.2f
#define ECAP 256           // per-head smem cache of edge scores (deg >> this is impossible here)

// ---------------- scratch (static device globals; no allocations) ----------------
__device__ float g_hA[(size_t)NN * HID];
__device__ float g_hB[(size_t)NN * HID];
__device__ float g_xl[(size_t)NN * HOUT];
__device__ float g_xr[(size_t)NN * HOUT];
__device__ int   g_deg[NN];
__device__ int   g_offs[NN + 1];
__device__ int   g_cursor[NN];
__device__ int   g_csr[EE];

// ---------------- CSR build ----------------
__global__ void k_zero_int(int* p, int n) {
    int i = blockIdx.x * blockDim.x + threadIdx.x;
    if (i < n) p[i] = 0;
}

__global__ void k_count_deg(const int* __restrict__ dst, int* __restrict__ deg, int e) {
    int i = blockIdx.x * blockDim.x + threadIdx.x;
    if (i < e) atomicAdd(&deg[dst[i]], 1);
}

// single-block exclusive scan over n (Hillis-Steele per 1024-chunk + carry)
__global__ void k_scan_excl(const int* __restrict__ deg, int* __restrict__ offs, int n) {
    __shared__ int sm[1024];
    __shared__ int carry;
    int tid = threadIdx.x;
    if (tid == 0) carry = 0;
    __syncthreads();
    for (int base = 0; base < n; base += 1024) {
        int v = (base + tid < n) ? deg[base + tid] : 0;
        sm[tid] = v;
        __syncthreads();
        for (int d = 1; d < 1024; d <<= 1) {
            int t = (tid >= d) ? sm[tid - d] : 0;
            __syncthreads();
            sm[tid] += t;
            __syncthreads();
        }
        int incl = sm[tid];
        if (base + tid < n) offs[base + tid] = carry + incl - v;
        int total = sm[1023];
        __syncthreads();
        if (tid == 0) carry += total;
        __syncthreads();
    }
    if (tid == 0) offs[n] = carry;
}

__global__ void k_copy_int(const int* __restrict__ a, int* __restrict__ b, int n) {
    int i = blockIdx.x * blockDim.x + threadIdx.x;
    if (i < n) b[i] = a[i];
}

__global__ void k_fill_csr(const int* __restrict__ src, const int* __restrict__ dst,
                           int* __restrict__ cursor, int* __restrict__ csr, int e) {
    int i = blockIdx.x * blockDim.x + threadIdx.x;
    if (i < e) {
        int p = atomicAdd(&cursor[dst[i]], 1);
        csr[p] = src[i];
    }
}

// ---------------- generic tiled fp32 GEMM: C = act(A[M,K] @ B[K,Nc] + bias) ----------------
// TM=64, TN=64, TK=32, 256 threads, 4x4 microtile per thread. Nc % 64 == 0, K % 32 == 0.
__global__ void k_gemm_bias_act(const float* __restrict__ A, const float* __restrict__ B,
                                const float* __restrict__ bias, float* __restrict__ C,
                                int M, int K, int Nc, int relu) {
    __shared__ float As[64][33];
    __shared__ float Bs[32][64];
    int tid = threadIdx.x;
    int tx = tid & 15, ty = tid >> 4;
    int bm = blockIdx.x * 64, bn = blockIdx.y * 64;
    float acc[4][4] = {};
    for (int kk = 0; kk < K; kk += 32) {
        #pragma unroll
        for (int i = 0; i < 8; i++) {
            int idx = tid + i * 256;
            int r = idx >> 5, c = idx & 31;
            int gr = bm + r;
            As[r][c] = (gr < M) ? A[(size_t)gr * K + kk + c] : 0.f;
        }
        #pragma unroll
        for (int i = 0; i < 8; i++) {
            int idx = tid + i * 256;
            int r = idx >> 6, c = idx & 63;
            Bs[r][c] = B[(size_t)(kk + r) * Nc + bn + c];
        }
        __syncthreads();
        #pragma unroll
        for (int k = 0; k < 32; k++) {
            float a[4], b[4];
            #pragma unroll
            for (int j = 0; j < 4; j++) a[j] = As[ty * 4 + j][k];
            #pragma unroll
            for (int j = 0; j < 4; j++) b[j] = Bs[k][tx * 4 + j];
            #pragma unroll
            for (int i = 0; i < 4; i++)
                #pragma unroll
                for (int j = 0; j < 4; j++)
                    acc[i][j] += a[i] * b[j];
        }
        __syncthreads();
    }
    #pragma unroll
    for (int i = 0; i < 4; i++) {
        int row = bm + ty * 4 + i;
        if (row >= M) continue;
        #pragma unroll
        for (int j = 0; j < 4; j++) {
            int col = bn + tx * 4 + j;
            float v = acc[i][j] + bias[col];
            if (relu) v = fmaxf(v, 0.f);
            C[(size_t)row * Nc + col] = v;
        }
    }
}

// ---------------- GATv2 edge kernel: one block (128 thr) per dst node, warp per head ----------------
__global__ void k_gat_edge(const float* __restrict__ xl, const float* __restrict__ xr,
                           const float* __restrict__ att,   // [HEADS,HID] (this layer)
                           const float* __restrict__ cbias, // [HID]
                           const float* __restrict__ hin, float* __restrict__ hout,
                           const int* __restrict__ offs, const int* __restrict__ csr) {
    int node = blockIdx.x;
    int w = threadIdx.x >> 5, lane = threadIdx.x & 31;
    __shared__ float es[HEADS][ECAP];
    __shared__ float hacc[HEADS][HID];

    int beg = offs[node], end = offs[node + 1];
    const float4 xrv = *(const float4*)(xr + (size_t)node * HOUT + w * HID + lane * 4);
    const float4 av  = *(const float4*)(att + w * HID + lane * 4);

    // pass 1: edge scores + running max
    float emax = -1e30f;
    for (int i = beg; i < end; i++) {
        int s = csr[i];
        float4 v = *(const float4*)(xl + (size_t)s * HOUT + w * HID + lane * 4);
        float m0 = v.x + xrv.x; m0 = m0 > 0.f ? m0 : NEG_SLOPE * m0;
        float m1 = v.y + xrv.y; m1 = m1 > 0.f ? m1 : NEG_SLOPE * m1;
        float m2 = v.z + xrv.z; m2 = m2 > 0.f ? m2 : NEG_SLOPE * m2;
        float m3 = v.w + xrv.w; m3 = m3 > 0.f ? m3 : NEG_SLOPE * m3;
        float p = av.x * m0 + av.y * m1 + av.z * m2 + av.w * m3;
        #pragma unroll
        for (int o = 16; o; o >>= 1) p += __shfl_xor_sync(0xffffffffu, p, o);
        if (lane == 0 && (i - beg) < ECAP) es[w][i - beg] = p;
        emax = fmaxf(emax, p);
    }
    __syncwarp();

    // pass 2: exp weights, denom, weighted aggregation of xl[src]
    float denom = 0.f;
    float4 acc = make_float4(0.f, 0.f, 0.f, 0.f);
    for (int i = beg; i < end; i++) {
        int s = csr[i];
        float4 v = *(const float4*)(xl + (size_t)s * HOUT + w * HID + lane * 4);
        float e;
        if ((i - beg) < ECAP) {
            e = es[w][i - beg];
        } else {
            float m0 = v.x + xrv.x; m0 = m0 > 0.f ? m0 : NEG_SLOPE * m0;
            float m1 = v.y + xrv.y; m1 = m1 > 0.f ? m1 : NEG_SLOPE * m1;
            float m2 = v.z + xrv.z; m2 = m2 > 0.f ? m2 : NEG_SLOPE * m2;
            float m3 = v.w + xrv.w; m3 = m3 > 0.f ? m3 : NEG_SLOPE * m3;
            float p = av.x * m0 + av.y * m1 + av.z * m2 + av.w * m3;
            #pragma unroll
            for (int o = 16; o; o >>= 1) p += __shfl_xor_sync(0xffffffffu, p, o);
            e = p;
        }
        float wt = expf(e - emax);
        denom += wt;
        acc.x += wt * v.x;
        acc.y += wt * v.y;
        acc.z += wt * v.z;
        acc.w += wt * v.w;
    }
    float inv = denom > 0.f ? 1.f / denom : 0.f;
    hacc[w][lane * 4 + 0] = acc.x * inv;
    hacc[w][lane * 4 + 1] = acc.y * inv;
    hacc[w][lane * 4 + 2] = acc.z * inv;
    hacc[w][lane * 4 + 3] = acc.w * inv;
    __syncthreads();

    int t = threadIdx.x;  // 128 threads == HID
    float sv = (hacc[0][t] + hacc[1][t] + hacc[2][t] + hacc[3][t]) * 0.25f
             + cbias[t] + hin[(size_t)node * HID + t];
    hout[(size_t)node * HID + t] = fmaxf(sv, 0.f);
}

// ---------------- final predictor head: scores = clip(z2 @ p3_W + b, -15, 15) ----------------
__global__ void k_pred3(const float* __restrict__ z2, const float* __restrict__ W,
                        const float* __restrict__ b, float* __restrict__ out, int n) {
    int warp = (blockIdx.x * blockDim.x + threadIdx.x) >> 5;
    int lane = threadIdx.x & 31;
    if (warp >= n) return;
    const float* zr = z2 + (size_t)warp * 64;
    float p = zr[lane] * W[lane] + zr[lane + 32] * W[lane + 32];
    #pragma unroll
    for (int o = 16; o; o >>= 1) p += __shfl_xor_sync(0xffffffffu, p, o);
    if (lane == 0) {
        float s = p + b[0];
        s = fminf(fmaxf(s, -15.f), 15.f);
        out[warp] = s;
    }
}

// ---------------- launch ----------------
extern "C" void kernel_launch(void* const* d_in, const int* in_sizes, int n_in,
                              void* d_out, int out_size) {
    const float* x      = (const float*)d_in[0];
    const int*   eidx   = (const int*)d_in[1];   // [2, E]: src row then dst row
    const float* emb_W  = (const float*)d_in[3];
    const float* emb_b  = (const float*)d_in[4];
    const float* Wl     = (const float*)d_in[5]; // [3,128,512]
    const float* bl     = (const float*)d_in[6]; // [3,512]
    const float* Wr     = (const float*)d_in[7];
    const float* br     = (const float*)d_in[8];
    const float* att    = (const float*)d_in[9];  // [3,4,128]
    const float* cbias  = (const float*)d_in[10]; // [3,128]
    const float* p1_W   = (const float*)d_in[11];
    const float* p1_b   = (const float*)d_in[12];
    const float* p2_W   = (const float*)d_in[13];
    const float* p2_b   = (const float*)d_in[14];
    const float* p3_W   = (const float*)d_in[15];
    const float* p3_b   = (const float*)d_in[16];
    float* out = (float*)d_out;

    const int* srcp = eidx;
    const int* dstp = eidx + EE;

    float *hA, *hB, *xl, *xr;
    int *deg, *offs, *cursor, *csr;
    cudaGetSymbolAddress((void**)&hA, g_hA);
    cudaGetSymbolAddress((void**)&hB, g_hB);
    cudaGetSymbolAddress((void**)&xl, g_xl);
    cudaGetSymbolAddress((void**)&xr, g_xr);
    cudaGetSymbolAddress((void**)&deg, g_deg);
    cudaGetSymbolAddress((void**)&offs, g_offs);
    cudaGetSymbolAddress((void**)&cursor, g_cursor);
    cudaGetSymbolAddress((void**)&csr, g_csr);

    // ---- CSR by dst ----
    k_zero_int<<<(NN + 255) / 256, 256>>>(deg, NN);
    k_count_deg<<<(EE + 255) / 256, 256>>>(dstp, deg, EE);
    k_scan_excl<<<1, 1024>>>(deg, offs, NN);
    k_copy_int<<<(NN + 255) / 256, 256>>>(offs, cursor, NN);
    k_fill_csr<<<(EE + 255) / 256, 256>>>(srcp, dstp, cursor, csr, EE);

    const int MB = (NN + 63) / 64;  // 782

    // ---- embedding: h = relu(x @ emb_W + emb_b) ----
    k_gemm_bias_act<<<dim3(MB, HID / 64), 256>>>(x, emb_W, emb_b, hA, NN, FIN, HID, 1);

    // ---- 3 GATv2 layers with residual + relu ----
    float* hc = hA;
    float* hn = hB;
    for (int l = 0; l < LAYERS; l++) {
        const float* Wl_l = Wl + (size_t)l * HID * HOUT;
        const float* Wr_l = Wr + (size_t)l * HID * HOUT;
        k_gemm_bias_act<<<dim3(MB, HOUT / 64), 256>>>(hc, Wl_l, bl + l * HOUT, xl, NN, HID, HOUT, 0);
        k_gemm_bias_act<<<dim3(MB, HOUT / 64), 256>>>(hc, Wr_l, br + l * HOUT, xr, NN, HID, HOUT, 0);
        k_gat_edge<<<NN, 128>>>(xl, xr, att + (size_t)l * HEADS * HID, cbias + l * HID,
                                hc, hn, offs, csr);
        float* tmp = hc; hc = hn; hn = tmp;
    }

    // ---- predictor MLP (reuse xl/xr as z1/z2 scratch) ----
    k_gemm_bias_act<<<dim3(MB, HID / 64), 256>>>(hc, p1_W, p1_b, xl, NN, HID, HID, 1);
    k_gemm_bias_act<<<dim3(MB, 1), 256>>>(xl, p2_W, p2_b, xr, NN, HID, 64, 1);
    k_pred3<<<(NN * 32 + 255) / 256, 256>>>(xr, p3_W, p3_b, out, NN);
}

// round 2
// speedup vs baseline: 1.5792x; 1.5792x over previous
#include <cuda_runtime.h>
#include <math.h>
#include <stdint.h>

#define NN   50000
#define EE   800000
#define FIN  64
#define HID  128
#define HEADS 4
#define HOUT 512           // HEADS*HID
#define LAYERS 3
#define NEG_SLOPE 0.2f

// ---------------- scratch (static device globals; no allocations) ----------------
__device__ float g_hA[(size_t)NN * HID];
__device__ float g_hB[(size_t)NN * HID];
__device__ float g_xl[(size_t)NN * HOUT];
__device__ float g_xr[(size_t)NN * HOUT];
__device__ int   g_deg[NN];
__device__ int   g_offs[NN + 1];
__device__ int   g_cursor[NN];
__device__ int   g_csr[EE];

// ---------------- CSR build ----------------
__global__ void k_zero_int(int* p, int n) {
    int i = blockIdx.x * blockDim.x + threadIdx.x;
    if (i < n) p[i] = 0;
}

__global__ void k_count_deg(const int* __restrict__ dst, int* __restrict__ deg, int e) {
    int i = blockIdx.x * blockDim.x + threadIdx.x;
    if (i < e) atomicAdd(&deg[dst[i]], 1);
}

// single-block exclusive scan over n (Hillis-Steele per 1024-chunk + carry)
__global__ void k_scan_excl(const int* __restrict__ deg, int* __restrict__ offs, int n) {
    __shared__ int sm[1024];
    __shared__ int carry;
    int tid = threadIdx.x;
    if (tid == 0) carry = 0;
    __syncthreads();
    for (int base = 0; base < n; base += 1024) {
        int v = (base + tid < n) ? deg[base + tid] : 0;
        sm[tid] = v;
        __syncthreads();
        for (int d = 1; d < 1024; d <<= 1) {
            int t = (tid >= d) ? sm[tid - d] : 0;
            __syncthreads();
            sm[tid] += t;
            __syncthreads();
        }
        int incl = sm[tid];
        if (base + tid < n) offs[base + tid] = carry + incl - v;
        int total = sm[1023];
        __syncthreads();
        if (tid == 0) carry += total;
        __syncthreads();
    }
    if (tid == 0) offs[n] = carry;
}

__global__ void k_copy_int(const int* __restrict__ a, int* __restrict__ b, int n) {
    int i = blockIdx.x * blockDim.x + threadIdx.x;
    if (i < n) b[i] = a[i];
}

__global__ void k_fill_csr(const int* __restrict__ src, const int* __restrict__ dst,
                           int* __restrict__ cursor, int* __restrict__ csr, int e) {
    int i = blockIdx.x * blockDim.x + threadIdx.x;
    if (i < e) {
        int p = atomicAdd(&cursor[dst[i]], 1);
        csr[p] = src[i];
    }
}

// ---------------- tf32 tensor-core GEMM ----------------
// C[M,N] = act(A[M,K] @ B[K,N] + bias), K % 32 == 0, N % 64 == 0.
// Block tile 128x64, 256 threads (8 warps), warp tile 32x32 via m16n8k8 tf32 mma.

__device__ __forceinline__ uint32_t f2tf(float f) {
    uint32_t u;
    asm("cvt.rna.tf32.f32 %0, %1;" : "=r"(u) : "f"(f));
    return u;
}

__device__ __forceinline__ void mma_tf32(float* d, const uint32_t* a, const uint32_t* b) {
    asm volatile(
        "mma.sync.aligned.m16n8k8.row.col.f32.tf32.tf32.f32 "
        "{%0,%1,%2,%3}, {%4,%5,%6,%7}, {%8,%9}, {%0,%1,%2,%3};"
        : "+f"(d[0]), "+f"(d[1]), "+f"(d[2]), "+f"(d[3])
        : "r"(a[0]), "r"(a[1]), "r"(a[2]), "r"(a[3]), "r"(b[0]), "r"(b[1]));
}

#define GBM 128
#define GBN 64
#define GBK 32
#define ASTRIDE 36   // 32 + 4 pad (keeps 16B alignment, kills A bank conflicts)
#define BSTRIDE 68   // 64 + 4 pad

__global__ __launch_bounds__(256) void k_gemm_tf32(
    const float* __restrict__ A, const float* __restrict__ B,
    const float* __restrict__ bias, float* __restrict__ C,
    int M, int K, int N, int relu) {
    __shared__ uint32_t As[GBM * ASTRIDE];
    __shared__ uint32_t Bs[GBK * BSTRIDE];
    int tid = threadIdx.x;
    int wid = tid >> 5, lane = tid & 31;
    int group = lane >> 2, lig = lane & 3;
    int wm = (wid & 3) * 32;       // warp row offset in block tile
    int wn = (wid >> 2) * 32;      // warp col offset in block tile
    int bm = blockIdx.x * GBM, bn = blockIdx.y * GBN;

    float acc[2][4][4];
    #pragma unroll
    for (int i = 0; i < 2; i++)
        #pragma unroll
        for (int j = 0; j < 4; j++)
            #pragma unroll
            for (int k = 0; k < 4; k++) acc[i][j][k] = 0.f;

    for (int kc = 0; kc < K; kc += GBK) {
        // A tile: 128x32 floats = 1024 float4, 4 per thread
        #pragma unroll
        for (int i = 0; i < 4; i++) {
            int idx = tid + i * 256;
            int r = idx >> 3;
            int c = (idx & 7) * 4;
            int gr = bm + r;
            float4 v = (gr < M) ? *(const float4*)(A + (size_t)gr * K + kc + c)
                                : make_float4(0.f, 0.f, 0.f, 0.f);
            uint32_t* p = &As[r * ASTRIDE + c];
            p[0] = f2tf(v.x); p[1] = f2tf(v.y); p[2] = f2tf(v.z); p[3] = f2tf(v.w);
        }
        // B tile: 32x64 floats = 512 float4, 2 per thread
        #pragma unroll
        for (int i = 0; i < 2; i++) {
            int idx = tid + i * 256;
            int r = idx >> 4;
            int c = (idx & 15) * 4;
            float4 v = *(const float4*)(B + (size_t)(kc + r) * N + bn + c);
            uint32_t* p = &Bs[r * BSTRIDE + c];
            p[0] = f2tf(v.x); p[1] = f2tf(v.y); p[2] = f2tf(v.z); p[3] = f2tf(v.w);
        }
        __syncthreads();
        #pragma unroll
        for (int k8 = 0; k8 < 4; k8++) {
            uint32_t af[2][4], bf[4][2];
            #pragma unroll
            for (int mt = 0; mt < 2; mt++) {
                int r0 = wm + mt * 16 + group;
                int c0 = k8 * 8 + lig;
                af[mt][0] = As[r0 * ASTRIDE + c0];
                af[mt][1] = As[(r0 + 8) * ASTRIDE + c0];
                af[mt][2] = As[r0 * ASTRIDE + c0 + 4];
                af[mt][3] = As[(r0 + 8) * ASTRIDE + c0 + 4];
            }
            #pragma unroll
            for (int nt = 0; nt < 4; nt++) {
                int c0 = wn + nt * 8 + group;
                int r0 = k8 * 8 + lig;
                bf[nt][0] = Bs[r0 * BSTRIDE + c0];
                bf[nt][1] = Bs[(r0 + 4) * BSTRIDE + c0];
            }
            #pragma unroll
            for (int mt = 0; mt < 2; mt++)
                #pragma unroll
                for (int nt = 0; nt < 4; nt++)
                    mma_tf32(acc[mt][nt], af[mt], bf[nt]);
        }
        __syncthreads();
    }

    // epilogue: bias + optional relu
    #pragma unroll
    for (int mt = 0; mt < 2; mt++) {
        #pragma unroll
        for (int nt = 0; nt < 4; nt++) {
            int col = bn + wn + nt * 8 + lig * 2;
            float b0 = bias[col], b1 = bias[col + 1];
            int row0 = bm + wm + mt * 16 + group;
            if (row0 < M) {
                float v0 = acc[mt][nt][0] + b0;
                float v1 = acc[mt][nt][1] + b1;
                if (relu) { v0 = fmaxf(v0, 0.f); v1 = fmaxf(v1, 0.f); }
                C[(size_t)row0 * N + col]     = v0;
                C[(size_t)row0 * N + col + 1] = v1;
            }
            int row1 = row0 + 8;
            if (row1 < M) {
                float v2 = acc[mt][nt][2] + b0;
                float v3 = acc[mt][nt][3] + b1;
                if (relu) { v2 = fmaxf(v2, 0.f); v3 = fmaxf(v3, 0.f); }
                C[(size_t)row1 * N + col]     = v2;
                C[(size_t)row1 * N + col + 1] = v3;
            }
        }
    }
}

// ---------------- GATv2 edge kernel: ONLINE softmax, single pass over edges ----------------
// One block (128 thr) per dst node, one warp per head.
__global__ void k_gat_edge(const float* __restrict__ xl, const float* __restrict__ xr,
                           const float* __restrict__ att,   // [HEADS,HID] (this layer)
                           const float* __restrict__ cbias, // [HID]
                           const float* __restrict__ hin, float* __restrict__ hout,
                           const int* __restrict__ offs, const int* __restrict__ csr) {
    int node = blockIdx.x;
    int w = threadIdx.x >> 5, lane = threadIdx.x & 31;
    __shared__ float hacc[HEADS][HID];

    int beg = offs[node], end = offs[node + 1];
    const float4 xrv = *(const float4*)(xr + (size_t)node * HOUT + w * HID + lane * 4);
    const float4 av  = *(const float4*)(att + w * HID + lane * 4);

    float emax = -1e30f;
    float denom = 0.f;
    float4 acc = make_float4(0.f, 0.f, 0.f, 0.f);
    for (int i = beg; i < end; i++) {
        int s = csr[i];
        float4 v = *(const float4*)(xl + (size_t)s * HOUT + w * HID + lane * 4);
        float m0 = v.x + xrv.x; m0 = m0 > 0.f ? m0 : NEG_SLOPE * m0;
        float m1 = v.y + xrv.y; m1 = m1 > 0.f ? m1 : NEG_SLOPE * m1;
        float m2 = v.z + xrv.z; m2 = m2 > 0.f ? m2 : NEG_SLOPE * m2;
        float m3 = v.w + xrv.w; m3 = m3 > 0.f ? m3 : NEG_SLOPE * m3;
        float p = av.x * m0 + av.y * m1 + av.z * m2 + av.w * m3;
        #pragma unroll
        for (int o = 16; o; o >>= 1) p += __shfl_xor_sync(0xffffffffu, p, o);
        // p is warp-uniform -> branch is divergence-free
        if (p > emax) {
            float sc = __expf(emax - p);   // first iter: exp(-huge) == 0, zeroes state
            denom *= sc;
            acc.x *= sc; acc.y *= sc; acc.z *= sc; acc.w *= sc;
            emax = p;
        }
        float wt = __expf(p - emax);
        denom += wt;
        acc.x += wt * v.x;
        acc.y += wt * v.y;
        acc.z += wt * v.z;
        acc.w += wt * v.w;
    }
    float inv = denom > 0.f ? 1.f / denom : 0.f;
    hacc[w][lane * 4 + 0] = acc.x * inv;
    hacc[w][lane * 4 + 1] = acc.y * inv;
    hacc[w][lane * 4 + 2] = acc.z * inv;
    hacc[w][lane * 4 + 3] = acc.w * inv;
    __syncthreads();

    int t = threadIdx.x;  // 128 threads == HID
    float sv = (hacc[0][t] + hacc[1][t] + hacc[2][t] + hacc[3][t]) * 0.25f
             + cbias[t] + hin[(size_t)node * HID + t];
    hout[(size_t)node * HID + t] = fmaxf(sv, 0.f);
}

// ---------------- final predictor head: scores = clip(z2 @ p3_W + b, -15, 15) ----------------
__global__ void k_pred3(const float* __restrict__ z2, const float* __restrict__ W,
                        const float* __restrict__ b, float* __restrict__ out, int n) {
    int warp = (blockIdx.x * blockDim.x + threadIdx.x) >> 5;
    int lane = threadIdx.x & 31;
    if (warp >= n) return;
    const float* zr = z2 + (size_t)warp * 64;
    float p = zr[lane] * W[lane] + zr[lane + 32] * W[lane + 32];
    #pragma unroll
    for (int o = 16; o; o >>= 1) p += __shfl_xor_sync(0xffffffffu, p, o);
    if (lane == 0) {
        float s = p + b[0];
        s = fminf(fmaxf(s, -15.f), 15.f);
        out[warp] = s;
    }
}

// ---------------- launch ----------------
extern "C" void kernel_launch(void* const* d_in, const int* in_sizes, int n_in,
                              void* d_out, int out_size) {
    const float* x      = (const float*)d_in[0];
    const int*   eidx   = (const int*)d_in[1];   // [2, E]: src row then dst row
    const float* emb_W  = (const float*)d_in[3];
    const float* emb_b  = (const float*)d_in[4];
    const float* Wl     = (const float*)d_in[5]; // [3,128,512]
    const float* bl     = (const float*)d_in[6]; // [3,512]
    const float* Wr     = (const float*)d_in[7];
    const float* br     = (const float*)d_in[8];
    const float* att    = (const float*)d_in[9];  // [3,4,128]
    const float* cbias  = (const float*)d_in[10]; // [3,128]
    const float* p1_W   = (const float*)d_in[11];
    const float* p1_b   = (const float*)d_in[12];
    const float* p2_W   = (const float*)d_in[13];
    const float* p2_b   = (const float*)d_in[14];
    const float* p3_W   = (const float*)d_in[15];
    const float* p3_b   = (const float*)d_in[16];
    float* out = (float*)d_out;

    const int* srcp = eidx;
    const int* dstp = eidx + EE;

    float *hA, *hB, *xl, *xr;
    int *deg, *offs, *cursor, *csr;
    cudaGetSymbolAddress((void**)&hA, g_hA);
    cudaGetSymbolAddress((void**)&hB, g_hB);
    cudaGetSymbolAddress((void**)&xl, g_xl);
    cudaGetSymbolAddress((void**)&xr, g_xr);
    cudaGetSymbolAddress((void**)&deg, g_deg);
    cudaGetSymbolAddress((void**)&offs, g_offs);
    cudaGetSymbolAddress((void**)&cursor, g_cursor);
    cudaGetSymbolAddress((void**)&csr, g_csr);

    // ---- CSR by dst ----
    k_zero_int<<<(NN + 255) / 256, 256>>>(deg, NN);
    k_count_deg<<<(EE + 255) / 256, 256>>>(dstp, deg, EE);
    k_scan_excl<<<1, 1024>>>(deg, offs, NN);
    k_copy_int<<<(NN + 255) / 256, 256>>>(offs, cursor, NN);
    k_fill_csr<<<(EE + 255) / 256, 256>>>(srcp, dstp, cursor, csr, EE);

    const int MB = (NN + GBM - 1) / GBM;  // 391

    // ---- embedding: h = relu(x @ emb_W + emb_b) ----
    k_gemm_tf32<<<dim3(MB, HID / GBN), 256>>>(x, emb_W, emb_b, hA, NN, FIN, HID, 1);

    // ---- 3 GATv2 layers with residual + relu ----
    float* hc = hA;
    float* hn = hB;
    for (int l = 0; l < LAYERS; l++) {
        const float* Wl_l = Wl + (size_t)l * HID * HOUT;
        const float* Wr_l = Wr + (size_t)l * HID * HOUT;
        k_gemm_tf32<<<dim3(MB, HOUT / GBN), 256>>>(hc, Wl_l, bl + l * HOUT, xl, NN, HID, HOUT, 0);
        k_gemm_tf32<<<dim3(MB, HOUT / GBN), 256>>>(hc, Wr_l, br + l * HOUT, xr, NN, HID, HOUT, 0);
        k_gat_edge<<<NN, 128>>>(xl, xr, att + (size_t)l * HEADS * HID, cbias + l * HID,
                                hc, hn, offs, csr);
        float* tmp = hc; hc = hn; hn = tmp;
    }

    // ---- predictor MLP (reuse xl/xr as z1/z2 scratch) ----
    k_gemm_tf32<<<dim3(MB, HID / GBN), 256>>>(hc, p1_W, p1_b, xl, NN, HID, HID, 1);
    k_gemm_tf32<<<dim3(MB, 1), 256>>>(xl, p2_W, p2_b, xr, NN, HID, 64, 1);
    k_pred3<<<(NN * 32 + 255) / 256, 256>>>(xr, p3_W, p3_b, out, NN);
}